// round 16
// baseline (speedup 1.0000x reference)
#include <cuda_runtime.h>
#include <cuda_fp16.h>

#define N_NODES 100000
#define E_EDGES 1600000
#define IN_C    32
#define HID     32
#define OUT_C   8
#define EDGE_D  16
#define GRAPH_D 16

// ---------------- device scratch ----------------
__device__ uint4 g_Prh[N_NODES * 2];        // fp16 P_r rows (32B), all biases folded
__device__ uint4 g_Pch[N_NODES * 2];        // fp16 P_c rows
__device__ uint4 g_mNh[N_NODES * 2];        // fp16 mN accumulator rows (32B)
__device__ float g_h2 [N_NODES * HID];
__device__ float g_t  [N_NODES];
__device__ float g_rcnt[N_NODES];
__device__ float g_ccnt[N_NODES];
__device__ float g_S0 [HID];
__device__ float g_S1 [HID];
// folded weights (built per-launch by k_fold)
__device__ float g_Wpr [IN_C * EDGE_D];
__device__ float g_Wpc [IN_C * EDGE_D];
__device__ float g_Wx  [IN_C * HID];
__device__ float g_bpr [EDGE_D];
__device__ float g_bna [HID];

__device__ __forceinline__ void red_add_v4h2(void* addr, unsigned a, unsigned b,
                                             unsigned c, unsigned d) {
    asm volatile("red.global.add.noftz.v4.f16x2 [%0], {%1,%2,%3,%4};"
                 :: "l"(addr), "r"(a), "r"(b), "r"(c), "r"(d) : "memory");
}

// ---------------- k_fold: build folded weight matrices ----------------
__global__ void __launch_bounds__(1024)
k_fold(const float* __restrict__ ga, const float* __restrict__ Wg,
       const float* __restrict__ bg,
       const float* __restrict__ Wn, const float* __restrict__ bn,
       const float* __restrict__ Wea, const float* __restrict__ bea,
       const float* __restrict__ Wna, const float* __restrict__ bna) {
    __shared__ float hG[GRAPH_D];
    int tid = threadIdx.x;
    if (tid < GRAPH_D) {
        float acc = bg[tid];
        #pragma unroll
        for (int k = 0; k < GRAPH_D; k++) acc += ga[k] * Wg[k * GRAPH_D + tid];
        hG[tid] = acc;
    }
    if (tid < HID) { g_S0[tid] = 0.f; g_S1[tid] = 0.f; }
    __syncthreads();

    if (tid < IN_C * EDGE_D) {
        int r = tid / EDGE_D, j = tid % EDGE_D;
        float apr = 0.f, apc = 0.f;
        #pragma unroll
        for (int k = 0; k < HID; k++) {
            float w = Wn[r * HID + k];
            apr += w * Wea[k * EDGE_D + j];
            apc += w * Wea[(32 + k) * EDGE_D + j];
        }
        g_Wpr[tid] = apr;
        g_Wpc[tid] = apc;
    }
    if (tid < IN_C * HID) {
        int r = tid / HID, j = tid % HID;
        float a = 0.f;
        #pragma unroll
        for (int k = 0; k < HID; k++)
            a += Wn[r * HID + k] * Wna[k * HID + j];
        g_Wx[tid] = a;
    }
    if (tid < EDGE_D) {
        float b = bea[tid];
        #pragma unroll
        for (int k = 0; k < GRAPH_D; k++) b += hG[k] * Wea[(80 + k) * EDGE_D + tid];
        #pragma unroll
        for (int k = 0; k < HID; k++)     b += bn[k] * Wea[k * EDGE_D + tid];
        g_bpr[tid] = b;
    }
    if (tid >= 32 && tid < 32 + HID) {
        int j = tid - 32;
        float b = bna[j];
        #pragma unroll
        for (int k = 0; k < GRAPH_D; k++) b += hG[k] * Wna[(48 + k) * HID + j];
        #pragma unroll
        for (int k = 0; k < HID; k++)     b += bn[k] * Wna[k * HID + j];
        g_bna[j] = b;
    }
}

// ---------------- stream-B: zero degrees, then degrees ----------------
__global__ void __launch_bounds__(256)
k_zeroDeg() {
    int n = blockIdx.x * blockDim.x + threadIdx.x;
    if (n < N_NODES) { g_rcnt[n] = 0.f; g_ccnt[n] = 0.f; g_t[n] = 0.f; }
}

__global__ void __launch_bounds__(256)
k_deg(const int* __restrict__ ei) {
    int e = blockIdx.x * blockDim.x + threadIdx.x;
    if (e >= E_EDGES) return;
    atomicAdd(&g_rcnt[ei[e]], 1.f);
    atomicAdd(&g_ccnt[ei[E_EDGES + e]], 1.f);
}

// ---------------- stream-B: t accumulation (after edge1, beside node2) ----------------
__global__ void __launch_bounds__(256)
k_edge2(const int* __restrict__ ei) {
    int e = blockIdx.x * blockDim.x + threadIdx.x;
    if (e >= E_EDGES) return;
    int row = ei[e];
    int col = ei[E_EDGES + e];
    float w = 1.f / fmaxf(g_ccnt[col], 1.f);
    atomicAdd(&g_t[row], w);
}

// ---------------- k_nodeP: x -> Pr/Pc (fp16) directly + zero mN ----------------
__global__ void __launch_bounds__(256)
k_nodeP(const float* __restrict__ x) {
    __shared__ float Wprs[IN_C * EDGE_D];
    __shared__ float Wpcs[IN_C * EDGE_D];
    __shared__ float bprs[EDGE_D];
    for (int t = threadIdx.x; t < IN_C * EDGE_D; t += blockDim.x) {
        Wprs[t] = g_Wpr[t];
        Wpcs[t] = g_Wpc[t];
    }
    if (threadIdx.x < EDGE_D) bprs[threadIdx.x] = g_bpr[threadIdx.x];
    __syncthreads();

    int n = blockIdx.x * blockDim.x + threadIdx.x;
    if (n >= N_NODES) return;

    uint4 z4 = make_uint4(0u, 0u, 0u, 0u);
    g_mNh[n * 2 + 0] = z4;
    g_mNh[n * 2 + 1] = z4;

    float pr[EDGE_D], pc[EDGE_D];
    #pragma unroll
    for (int j = 0; j < EDGE_D; j++) { pr[j] = bprs[j]; pc[j] = 0.f; }

    const float4* xr = reinterpret_cast<const float4*>(x + (size_t)n * IN_C);
    #pragma unroll
    for (int k4 = 0; k4 < IN_C / 4; k4++) {
        float4 v = xr[k4];
        float vv[4] = {v.x, v.y, v.z, v.w};
        #pragma unroll
        for (int q = 0; q < 4; q++) {
            float xv = vv[q];
            int k = k4 * 4 + q;
            #pragma unroll
            for (int j = 0; j < EDGE_D; j++) {
                pr[j] += xv * Wprs[k * EDGE_D + j];
                pc[j] += xv * Wpcs[k * EDGE_D + j];
            }
        }
    }
    union { __half2 h2[8]; uint4 u4[2]; } pk, qk;
    #pragma unroll
    for (int j = 0; j < 8; j++) {
        pk.h2[j] = __floats2half2_rn(pr[2*j], pr[2*j+1]);
        qk.h2[j] = __floats2half2_rn(pc[2*j], pc[2*j+1]);
    }
    g_Prh[n * 2 + 0] = pk.u4[0];
    g_Prh[n * 2 + 1] = pk.u4[1];
    g_Pch[n * 2 + 0] = qk.u4[0];
    g_Pch[n * 2 + 1] = qk.u4[1];
}

// ---------------- edge pass 1 — fused, FULL-FP16 matmul (HFMA2), clean indexing ----------------
// 4 lanes/edge. Lane c owns output channels [4c,4c+4). E*4/256 exact.
// Wch layout (halfs): Wch[c*64 + k*4 + jj] = Wc[k][4c+jj], k=0..15, jj=0..3.
// As half2:           wh2[c*32 + k*2 + p]  = (Wc[k][4c+2p], Wc[k][4c+2p+1]).
__global__ void __launch_bounds__(256)
k_edge1(const int* __restrict__ ei,
        const float* __restrict__ edge_attr,
        const float* __restrict__ Wea) {
    __shared__ __half  Wch[4 * 64];
    __shared__ __half2 eas[256 * 2];        // staged ea (fp16): slot t*2+p holds (k=4c+2p, k=4c+2p+1)
    if (threadIdx.x < 256) {
        float w = Wea[64 * EDGE_D + threadIdx.x];       // element [k][j], k=tid>>4, j=tid&15
        int k = threadIdx.x >> 4, j = threadIdx.x & 15;
        Wch[(j >> 2) * 64 + k * 4 + (j & 3)] = __float2half(w);
    }
    __syncthreads();

    int t = blockIdx.x * blockDim.x + threadIdx.x;
    int e = t >> 2;
    int c = threadIdx.x & 3;

    int row = ei[e];
    int col = ei[E_EDGES + e];

    uint2 pru = reinterpret_cast<const uint2*>(g_Prh)[(size_t)row * 4 + c];
    uint2 pcu = reinterpret_cast<const uint2*>(g_Pch)[(size_t)col * 4 + c];

    float4 ea = *reinterpret_cast<const float4*>(edge_attr + (size_t)e * EDGE_D + c * 4);
    eas[threadIdx.x * 2 + 0] = __floats2half2_rn(ea.x, ea.y);   // (k=4c,   k=4c+1)
    eas[threadIdx.x * 2 + 1] = __floats2half2_rn(ea.z, ea.w);   // (k=4c+2, k=4c+3)
    __syncwarp();

    // group's 16 ea values, ordered: evs[q] = (k=2q, k=2q+1), q=0..7
    const __half2* eg = eas + (threadIdx.x & ~3) * 2;

    // fp16 accumulators initialized from the gathers
    __half2 acc01 = __hadd2(*reinterpret_cast<__half2*>(&pru.x),
                            *reinterpret_cast<__half2*>(&pcu.x));
    __half2 acc23 = __hadd2(*reinterpret_cast<__half2*>(&pru.y),
                            *reinterpret_cast<__half2*>(&pcu.y));

    const __half2* wh2 = reinterpret_cast<const __half2*>(Wch) + c * 32;

    #pragma unroll
    for (int q = 0; q < 8; q++) {
        __half2 evp = eg[q];                 // (k=2q, k=2q+1)
        __half2 evl = __low2half2(evp);      // splat k=2q
        __half2 evh = __high2half2(evp);     // splat k=2q+1
        acc01 = __hfma2(evl, wh2[(2*q)   * 2 + 0], acc01);
        acc23 = __hfma2(evl, wh2[(2*q)   * 2 + 1], acc23);
        acc01 = __hfma2(evh, wh2[(2*q+1) * 2 + 0], acc01);
        acc23 = __hfma2(evh, wh2[(2*q+1) * 2 + 1], acc23);
    }

    __half2 z2 = __float2half2_rn(0.f);
    acc01 = __hmax2(acc01, z2);
    acc23 = __hmax2(acc23, z2);

    unsigned a0 = *reinterpret_cast<unsigned*>(&acc01);
    unsigned a1 = *reinterpret_cast<unsigned*>(&acc23);
    unsigned b0 = __shfl_xor_sync(0xFFFFFFFFu, a0, 1, 4);
    unsigned b1 = __shfl_xor_sync(0xFFFFFFFFu, a1, 1, 4);
    if ((c & 1) == 0) {
        __half* base = reinterpret_cast<__half*>(g_mNh + (size_t)row * 2) + (c >> 1) * 8;
        red_add_v4h2(base, a0, a1, b0, b1);
    }
}

// ---------------- node aggregator -> h_i2 — 2 threads/node ----------------
__global__ void __launch_bounds__(256)
k_node2(const float* __restrict__ x, const float* __restrict__ Wna) {
    __shared__ float Wxs[IN_C * HID];
    __shared__ float Wms[EDGE_D * HID];
    __shared__ float base_s[HID];
    for (int t = threadIdx.x; t < IN_C * HID; t += blockDim.x) Wxs[t] = g_Wx[t];
    for (int t = threadIdx.x; t < EDGE_D * HID; t += blockDim.x)
        Wms[t] = Wna[32 * HID + t];
    if (threadIdx.x < HID) base_s[threadIdx.x] = g_bna[threadIdx.x];
    __syncthreads();

    int t = blockIdx.x * blockDim.x + threadIdx.x;
    int n = t >> 1;
    if (n >= N_NODES) return;
    int h = t & 1;

    float acc[16];
    #pragma unroll
    for (int j = 0; j < 16; j++) acc[j] = base_s[h * 16 + j];

    const float4* xr = reinterpret_cast<const float4*>(x + (size_t)n * IN_C);
    #pragma unroll
    for (int k4 = 0; k4 < IN_C / 4; k4++) {
        float4 v = xr[k4];
        float vv[4] = {v.x, v.y, v.z, v.w};
        #pragma unroll
        for (int q = 0; q < 4; q++) {
            float xv = vv[q];
            int k = k4 * 4 + q;
            #pragma unroll
            for (int j = 0; j < 16; j++) acc[j] += xv * Wxs[k * HID + h * 16 + j];
        }
    }
    float inv_c = 1.f / fmaxf(g_rcnt[n], 1.f);
    union { uint4 u4[2]; __half2 h2[8]; } mu;
    mu.u4[0] = g_mNh[n * 2 + 0];
    mu.u4[1] = g_mNh[n * 2 + 1];
    #pragma unroll
    for (int p = 0; p < 8; p++) {
        float2 mf = __half22float2(mu.h2[p]);
        float m0 = mf.x * inv_c;
        float m1 = mf.y * inv_c;
        int k0 = 2 * p;
        #pragma unroll
        for (int j = 0; j < 16; j++) {
            acc[j] += m0 * Wms[k0 * HID + h * 16 + j];
            acc[j] += m1 * Wms[(k0 + 1) * HID + h * 16 + j];
        }
    }
    float4* h2o = reinterpret_cast<float4*>(g_h2 + (size_t)n * HID + h * 16);
    #pragma unroll
    for (int j4 = 0; j4 < 4; j4++)
        h2o[j4] = make_float4(fmaxf(acc[j4*4], 0.f),   fmaxf(acc[j4*4+1], 0.f),
                              fmaxf(acc[j4*4+2], 0.f), fmaxf(acc[j4*4+3], 0.f));
}

// ---------------- reduce S0 = sum h_i2, S1 = sum t*h_i2 ----------------
__global__ void __launch_bounds__(256)
k_reduce() {
    int lane = threadIdx.x & 31;
    int warp = (blockIdx.x * blockDim.x + threadIdx.x) >> 5;
    int nwarps = (gridDim.x * blockDim.x) >> 5;

    float s0 = 0.f, s1 = 0.f;
    for (int n = warp; n < N_NODES; n += nwarps) {
        float h = g_h2[(size_t)n * HID + lane];
        float tv = g_t[n];
        s0 += h;
        s1 += tv * h;
    }
    atomicAdd(&g_S0[lane], s0);
    atomicAdd(&g_S1[lane], s1);
}

// ---------------- pooled linear + log_softmax ----------------
__global__ void k_final(const float* __restrict__ Wl, const float* __restrict__ bl,
                        const float* __restrict__ Wr, float* __restrict__ out) {
    __shared__ float p[OUT_C];
    int j = threadIdx.x;
    if (j < OUT_C) {
        float acc = 0.f;
        #pragma unroll
        for (int k = 0; k < HID; k++)
            acc += g_S1[k] * Wl[k * OUT_C + j] + g_S0[k] * Wr[k * OUT_C + j];
        p[j] = bl[j] + acc * (1.f / (float)N_NODES);
    }
    __syncthreads();
    if (j == 0) {
        float mx = -1e30f;
        #pragma unroll
        for (int i = 0; i < OUT_C; i++) mx = fmaxf(mx, p[i]);
        float se = 0.f;
        #pragma unroll
        for (int i = 0; i < OUT_C; i++) se += expf(p[i] - mx);
        float lse = mx + logf(se);
        #pragma unroll
        for (int i = 0; i < OUT_C; i++) out[i] = p[i] - lse;
    }
}

// ---------------- launch ----------------
extern "C" void kernel_launch(void* const* d_in, const int* in_sizes, int n_in,
                              void* d_out, int out_size) {
    const float* x          = (const float*)d_in[0];
    const float* edge_attr  = (const float*)d_in[1];
    const float* graph_attr = (const float*)d_in[2];
    const int*   edge_index = (const int*)  d_in[3];
    const float* W_node     = (const float*)d_in[5];
    const float* b_node     = (const float*)d_in[6];
    const float* W_graph    = (const float*)d_in[7];
    const float* b_graph    = (const float*)d_in[8];
    const float* W_edge_agg = (const float*)d_in[9];
    const float* b_edge_agg = (const float*)d_in[10];
    const float* W_node_agg = (const float*)d_in[11];
    const float* b_node_agg = (const float*)d_in[12];
    const float* W_sage_l   = (const float*)d_in[13];
    const float* b_sage_l   = (const float*)d_in[14];
    const float* W_sage_r   = (const float*)d_in[15];
    float* out = (float*)d_out;

    static cudaStream_t sB = nullptr;
    static cudaEvent_t evFork = nullptr, evDeg = nullptr, evE1 = nullptr, evT = nullptr;
    if (sB == nullptr) {
        cudaStreamCreateWithFlags(&sB, cudaStreamNonBlocking);
        cudaEventCreateWithFlags(&evFork, cudaEventDisableTiming);
        cudaEventCreateWithFlags(&evDeg, cudaEventDisableTiming);
        cudaEventCreateWithFlags(&evE1, cudaEventDisableTiming);
        cudaEventCreateWithFlags(&evT, cudaEventDisableTiming);
    }

    const int TB = 256;
    const int nodeBlocks  = (N_NODES + TB - 1) / TB;
    const int node2Blocks = (N_NODES * 2 + TB - 1) / TB;
    const int edge1Blocks = (E_EDGES * 4) / TB;
    const int edgeBlocks  = (E_EDGES + TB - 1) / TB;

    k_fold<<<1, 1024>>>(graph_attr, W_graph, b_graph, W_node, b_node,
                        W_edge_agg, b_edge_agg, W_node_agg, b_node_agg);

    // stream B: degrees, overlapped ONLY with compute-bound k_nodeP
    cudaEventRecord(evFork, 0);
    cudaStreamWaitEvent(sB, evFork, 0);
    k_zeroDeg<<<nodeBlocks, TB, 0, sB>>>();
    k_deg<<<edgeBlocks, TB, 0, sB>>>(edge_index);
    cudaEventRecord(evDeg, sB);

    // main stream
    k_nodeP<<<nodeBlocks, TB>>>(x);
    cudaStreamWaitEvent(0, evDeg, 0);
    k_edge1<<<edge1Blocks, TB>>>(edge_index, edge_attr, W_edge_agg);
    cudaEventRecord(evE1, 0);

    // stream B: t accumulation beside node2
    cudaStreamWaitEvent(sB, evE1, 0);
    k_edge2<<<edgeBlocks, TB, 0, sB>>>(edge_index);
    cudaEventRecord(evT, sB);

    k_node2<<<node2Blocks, TB>>>(x, W_node_agg);

    cudaStreamWaitEvent(0, evT, 0);
    k_reduce<<<128, TB>>>();
    k_final<<<1, 32>>>(W_sage_l, b_sage_l, W_sage_r, out);
}

// round 17
// speedup vs baseline: 1.3834x; 1.3834x over previous
#include <cuda_runtime.h>
#include <cuda_fp16.h>

#define N_NODES 100000
#define E_EDGES 1600000
#define IN_C    32
#define HID     32
#define OUT_C   8
#define EDGE_D  16
#define GRAPH_D 16

// ---------------- device scratch ----------------
__device__ uint4 g_Prh[N_NODES * 2];        // fp16 P_r rows (32B), all biases folded
__device__ uint4 g_Pch[N_NODES * 2];        // fp16 P_c rows
__device__ uint4 g_mNh[N_NODES * 2];        // fp16 mN accumulator rows (32B)
__device__ float g_h2 [N_NODES * HID];
__device__ float g_t  [N_NODES];
__device__ float g_rcnt[N_NODES];
__device__ float g_ccnt[N_NODES];
__device__ float g_S0 [HID];
__device__ float g_S1 [HID];
// folded weights (built per-launch by k_fold)
__device__ float g_Wpr [IN_C * EDGE_D];
__device__ float g_Wpc [IN_C * EDGE_D];
__device__ float g_Wx  [IN_C * HID];
__device__ float g_bpr [EDGE_D];
__device__ float g_bna [HID];

__device__ __forceinline__ void red_add_v4h2(void* addr, unsigned a, unsigned b,
                                             unsigned c, unsigned d) {
    asm volatile("red.global.add.noftz.v4.f16x2 [%0], {%1,%2,%3,%4};"
                 :: "l"(addr), "r"(a), "r"(b), "r"(c), "r"(d) : "memory");
}

// ---------------- k_fold: build folded weight matrices ----------------
__global__ void __launch_bounds__(1024)
k_fold(const float* __restrict__ ga, const float* __restrict__ Wg,
       const float* __restrict__ bg,
       const float* __restrict__ Wn, const float* __restrict__ bn,
       const float* __restrict__ Wea, const float* __restrict__ bea,
       const float* __restrict__ Wna, const float* __restrict__ bna) {
    __shared__ float hG[GRAPH_D];
    int tid = threadIdx.x;
    if (tid < GRAPH_D) {
        float acc = bg[tid];
        #pragma unroll
        for (int k = 0; k < GRAPH_D; k++) acc += ga[k] * Wg[k * GRAPH_D + tid];
        hG[tid] = acc;
    }
    if (tid < HID) { g_S0[tid] = 0.f; g_S1[tid] = 0.f; }
    __syncthreads();

    if (tid < IN_C * EDGE_D) {
        int r = tid / EDGE_D, j = tid % EDGE_D;
        float apr = 0.f, apc = 0.f;
        #pragma unroll
        for (int k = 0; k < HID; k++) {
            float w = Wn[r * HID + k];
            apr += w * Wea[k * EDGE_D + j];
            apc += w * Wea[(32 + k) * EDGE_D + j];
        }
        g_Wpr[tid] = apr;
        g_Wpc[tid] = apc;
    }
    if (tid < IN_C * HID) {
        int r = tid / HID, j = tid % HID;
        float a = 0.f;
        #pragma unroll
        for (int k = 0; k < HID; k++)
            a += Wn[r * HID + k] * Wna[k * HID + j];
        g_Wx[tid] = a;
    }
    if (tid < EDGE_D) {
        float b = bea[tid];
        #pragma unroll
        for (int k = 0; k < GRAPH_D; k++) b += hG[k] * Wea[(80 + k) * EDGE_D + tid];
        #pragma unroll
        for (int k = 0; k < HID; k++)     b += bn[k] * Wea[k * EDGE_D + tid];
        g_bpr[tid] = b;
    }
    if (tid >= 32 && tid < 32 + HID) {
        int j = tid - 32;
        float b = bna[j];
        #pragma unroll
        for (int k = 0; k < GRAPH_D; k++) b += hG[k] * Wna[(48 + k) * HID + j];
        #pragma unroll
        for (int k = 0; k < HID; k++)     b += bn[k] * Wna[k * HID + j];
        g_bna[j] = b;
    }
}

// ---------------- stream-B: zero degrees, then degrees ----------------
__global__ void __launch_bounds__(256)
k_zeroDeg() {
    int n = blockIdx.x * blockDim.x + threadIdx.x;
    if (n < N_NODES) { g_rcnt[n] = 0.f; g_ccnt[n] = 0.f; g_t[n] = 0.f; }
}

__global__ void __launch_bounds__(256)
k_deg(const int* __restrict__ ei) {
    int e = blockIdx.x * blockDim.x + threadIdx.x;
    if (e >= E_EDGES) return;
    atomicAdd(&g_rcnt[ei[e]], 1.f);
    atomicAdd(&g_ccnt[ei[E_EDGES + e]], 1.f);
}

// ---------------- stream-B: t accumulation (after edge1, beside node2) ----------------
__global__ void __launch_bounds__(256)
k_edge2(const int* __restrict__ ei) {
    int e = blockIdx.x * blockDim.x + threadIdx.x;
    if (e >= E_EDGES) return;
    int row = ei[e];
    int col = ei[E_EDGES + e];
    float w = 1.f / fmaxf(g_ccnt[col], 1.f);
    atomicAdd(&g_t[row], w);
}

// ---------------- k_nodeP: x -> Pr/Pc (fp16) directly + zero mN ----------------
__global__ void __launch_bounds__(256)
k_nodeP(const float* __restrict__ x) {
    __shared__ float Wprs[IN_C * EDGE_D];
    __shared__ float Wpcs[IN_C * EDGE_D];
    __shared__ float bprs[EDGE_D];
    for (int t = threadIdx.x; t < IN_C * EDGE_D; t += blockDim.x) {
        Wprs[t] = g_Wpr[t];
        Wpcs[t] = g_Wpc[t];
    }
    if (threadIdx.x < EDGE_D) bprs[threadIdx.x] = g_bpr[threadIdx.x];
    __syncthreads();

    int n = blockIdx.x * blockDim.x + threadIdx.x;
    if (n >= N_NODES) return;

    uint4 z4 = make_uint4(0u, 0u, 0u, 0u);
    g_mNh[n * 2 + 0] = z4;
    g_mNh[n * 2 + 1] = z4;

    float pr[EDGE_D], pc[EDGE_D];
    #pragma unroll
    for (int j = 0; j < EDGE_D; j++) { pr[j] = bprs[j]; pc[j] = 0.f; }

    const float4* xr = reinterpret_cast<const float4*>(x + (size_t)n * IN_C);
    #pragma unroll
    for (int k4 = 0; k4 < IN_C / 4; k4++) {
        float4 v = xr[k4];
        float vv[4] = {v.x, v.y, v.z, v.w};
        #pragma unroll
        for (int q = 0; q < 4; q++) {
            float xv = vv[q];
            int k = k4 * 4 + q;
            #pragma unroll
            for (int j = 0; j < EDGE_D; j++) {
                pr[j] += xv * Wprs[k * EDGE_D + j];
                pc[j] += xv * Wpcs[k * EDGE_D + j];
            }
        }
    }
    union { __half2 h2[8]; uint4 u4[2]; } pk, qk;
    #pragma unroll
    for (int j = 0; j < 8; j++) {
        pk.h2[j] = __floats2half2_rn(pr[2*j], pr[2*j+1]);
        qk.h2[j] = __floats2half2_rn(pc[2*j], pc[2*j+1]);
    }
    g_Prh[n * 2 + 0] = pk.u4[0];
    g_Prh[n * 2 + 1] = pk.u4[1];
    g_Pch[n * 2 + 0] = qk.u4[0];
    g_Pch[n * 2 + 1] = qk.u4[1];
}

// ---------------- edge pass 1 — grid-stride, REGISTER-RESIDENT fp16 weights ----------------
// 4 lanes/edge; lane c owns output channels [4c,4c+4), weights in 32 half2 regs.
#define E1_BLOCKS 2500
__global__ void __launch_bounds__(256)
k_edge1(const int* __restrict__ ei,
        const float* __restrict__ edge_attr,
        const float* __restrict__ Wea) {
    __shared__ __half2 eas[256 * 2];        // staged ea (fp16): thread t -> slots [2t, 2t+2)
    int c = threadIdx.x & 3;

    // load this lane's weight slice ONCE: Wc[k][4c..4c+4) for k=0..15
    __half2 whA[16], whB[16];
    {
        const float4* wrow = reinterpret_cast<const float4*>(Wea + 64 * EDGE_D);
        #pragma unroll
        for (int k = 0; k < 16; k++) {
            float4 wv = wrow[k * 4 + c];
            whA[k] = __floats2half2_rn(wv.x, wv.y);
            whB[k] = __floats2half2_rn(wv.z, wv.w);
        }
    }

    const int gstride = E1_BLOCKS * 64;     // 64 groups per block
    for (int g = blockIdx.x * 64 + (threadIdx.x >> 2); g < E_EDGES; g += gstride) {
        int row = ei[g];
        int col = ei[E_EDGES + g];

        uint2 pru = reinterpret_cast<const uint2*>(g_Prh)[(size_t)row * 4 + c];
        uint2 pcu = reinterpret_cast<const uint2*>(g_Pch)[(size_t)col * 4 + c];

        float4 ea = *reinterpret_cast<const float4*>(edge_attr + (size_t)g * EDGE_D + c * 4);
        eas[threadIdx.x * 2 + 0] = __floats2half2_rn(ea.x, ea.y);   // (k=4c,   4c+1)
        eas[threadIdx.x * 2 + 1] = __floats2half2_rn(ea.z, ea.w);   // (k=4c+2, 4c+3)
        __syncwarp();

        // group's 16 ea values: 8 half2 = 32B = 2 LDS.128
        const uint4* egq = reinterpret_cast<const uint4*>(eas + (threadIdx.x & ~3) * 2);
        uint4 e0 = egq[0];
        uint4 e1 = egq[1];
        unsigned evs[8] = {e0.x, e0.y, e0.z, e0.w, e1.x, e1.y, e1.z, e1.w};
        // evs[q] holds (k0, k0+1) with k0 = (q>>1)*4 + (q&1)*2

        __half2 acc01 = __hadd2(*reinterpret_cast<__half2*>(&pru.x),
                                *reinterpret_cast<__half2*>(&pcu.x));
        __half2 acc23 = __hadd2(*reinterpret_cast<__half2*>(&pru.y),
                                *reinterpret_cast<__half2*>(&pcu.y));

        #pragma unroll
        for (int q = 0; q < 8; q++) {
            const int k0 = (q >> 1) * 4 + (q & 1) * 2;
            __half2 evp = *reinterpret_cast<__half2*>(&evs[q]);
            __half2 evl = __low2half2(evp);
            __half2 evh = __high2half2(evp);
            acc01 = __hfma2(evl, whA[k0],     acc01);
            acc23 = __hfma2(evl, whB[k0],     acc23);
            acc01 = __hfma2(evh, whA[k0 + 1], acc01);
            acc23 = __hfma2(evh, whB[k0 + 1], acc23);
        }

        __half2 z2 = __float2half2_rn(0.f);
        acc01 = __hmax2(acc01, z2);
        acc23 = __hmax2(acc23, z2);

        unsigned a0 = *reinterpret_cast<unsigned*>(&acc01);
        unsigned a1 = *reinterpret_cast<unsigned*>(&acc23);
        // full-mask shfl converges the warp: LDS reads above are complete before
        // the next iteration's staging store.
        unsigned b0 = __shfl_xor_sync(0xFFFFFFFFu, a0, 1, 4);
        unsigned b1 = __shfl_xor_sync(0xFFFFFFFFu, a1, 1, 4);
        if ((c & 1) == 0) {
            __half* base = reinterpret_cast<__half*>(g_mNh + (size_t)row * 2) + (c >> 1) * 8;
            red_add_v4h2(base, a0, a1, b0, b1);
        }
    }
}

// ---------------- node aggregator -> h_i2 — 2 threads/node ----------------
__global__ void __launch_bounds__(256)
k_node2(const float* __restrict__ x, const float* __restrict__ Wna) {
    __shared__ float Wxs[IN_C * HID];
    __shared__ float Wms[EDGE_D * HID];
    __shared__ float base_s[HID];
    for (int t = threadIdx.x; t < IN_C * HID; t += blockDim.x) Wxs[t] = g_Wx[t];
    for (int t = threadIdx.x; t < EDGE_D * HID; t += blockDim.x)
        Wms[t] = Wna[32 * HID + t];
    if (threadIdx.x < HID) base_s[threadIdx.x] = g_bna[threadIdx.x];
    __syncthreads();

    int t = blockIdx.x * blockDim.x + threadIdx.x;
    int n = t >> 1;
    if (n >= N_NODES) return;
    int h = t & 1;

    float acc[16];
    #pragma unroll
    for (int j = 0; j < 16; j++) acc[j] = base_s[h * 16 + j];

    const float4* xr = reinterpret_cast<const float4*>(x + (size_t)n * IN_C);
    #pragma unroll
    for (int k4 = 0; k4 < IN_C / 4; k4++) {
        float4 v = xr[k4];
        float vv[4] = {v.x, v.y, v.z, v.w};
        #pragma unroll
        for (int q = 0; q < 4; q++) {
            float xv = vv[q];
            int k = k4 * 4 + q;
            #pragma unroll
            for (int j = 0; j < 16; j++) acc[j] += xv * Wxs[k * HID + h * 16 + j];
        }
    }
    float inv_c = 1.f / fmaxf(g_rcnt[n], 1.f);
    union { uint4 u4[2]; __half2 h2[8]; } mu;
    mu.u4[0] = g_mNh[n * 2 + 0];
    mu.u4[1] = g_mNh[n * 2 + 1];
    #pragma unroll
    for (int p = 0; p < 8; p++) {
        float2 mf = __half22float2(mu.h2[p]);
        float m0 = mf.x * inv_c;
        float m1 = mf.y * inv_c;
        int k0 = 2 * p;
        #pragma unroll
        for (int j = 0; j < 16; j++) {
            acc[j] += m0 * Wms[k0 * HID + h * 16 + j];
            acc[j] += m1 * Wms[(k0 + 1) * HID + h * 16 + j];
        }
    }
    float4* h2o = reinterpret_cast<float4*>(g_h2 + (size_t)n * HID + h * 16);
    #pragma unroll
    for (int j4 = 0; j4 < 4; j4++)
        h2o[j4] = make_float4(fmaxf(acc[j4*4], 0.f),   fmaxf(acc[j4*4+1], 0.f),
                              fmaxf(acc[j4*4+2], 0.f), fmaxf(acc[j4*4+3], 0.f));
}

// ---------------- reduce S0 = sum h_i2, S1 = sum t*h_i2 ----------------
__global__ void __launch_bounds__(256)
k_reduce() {
    int lane = threadIdx.x & 31;
    int warp = (blockIdx.x * blockDim.x + threadIdx.x) >> 5;
    int nwarps = (gridDim.x * blockDim.x) >> 5;

    float s0 = 0.f, s1 = 0.f;
    for (int n = warp; n < N_NODES; n += nwarps) {
        float h = g_h2[(size_t)n * HID + lane];
        float tv = g_t[n];
        s0 += h;
        s1 += tv * h;
    }
    atomicAdd(&g_S0[lane], s0);
    atomicAdd(&g_S1[lane], s1);
}

// ---------------- pooled linear + log_softmax ----------------
__global__ void k_final(const float* __restrict__ Wl, const float* __restrict__ bl,
                        const float* __restrict__ Wr, float* __restrict__ out) {
    __shared__ float p[OUT_C];
    int j = threadIdx.x;
    if (j < OUT_C) {
        float acc = 0.f;
        #pragma unroll
        for (int k = 0; k < HID; k++)
            acc += g_S1[k] * Wl[k * OUT_C + j] + g_S0[k] * Wr[k * OUT_C + j];
        p[j] = bl[j] + acc * (1.f / (float)N_NODES);
    }
    __syncthreads();
    if (j == 0) {
        float mx = -1e30f;
        #pragma unroll
        for (int i = 0; i < OUT_C; i++) mx = fmaxf(mx, p[i]);
        float se = 0.f;
        #pragma unroll
        for (int i = 0; i < OUT_C; i++) se += expf(p[i] - mx);
        float lse = mx + logf(se);
        #pragma unroll
        for (int i = 0; i < OUT_C; i++) out[i] = p[i] - lse;
    }
}

// ---------------- launch ----------------
extern "C" void kernel_launch(void* const* d_in, const int* in_sizes, int n_in,
                              void* d_out, int out_size) {
    const float* x          = (const float*)d_in[0];
    const float* edge_attr  = (const float*)d_in[1];
    const float* graph_attr = (const float*)d_in[2];
    const int*   edge_index = (const int*)  d_in[3];
    const float* W_node     = (const float*)d_in[5];
    const float* b_node     = (const float*)d_in[6];
    const float* W_graph    = (const float*)d_in[7];
    const float* b_graph    = (const float*)d_in[8];
    const float* W_edge_agg = (const float*)d_in[9];
    const float* b_edge_agg = (const float*)d_in[10];
    const float* W_node_agg = (const float*)d_in[11];
    const float* b_node_agg = (const float*)d_in[12];
    const float* W_sage_l   = (const float*)d_in[13];
    const float* b_sage_l   = (const float*)d_in[14];
    const float* W_sage_r   = (const float*)d_in[15];
    float* out = (float*)d_out;

    static cudaStream_t sB = nullptr;
    static cudaEvent_t evFork = nullptr, evDeg = nullptr, evE1 = nullptr, evT = nullptr;
    if (sB == nullptr) {
        cudaStreamCreateWithFlags(&sB, cudaStreamNonBlocking);
        cudaEventCreateWithFlags(&evFork, cudaEventDisableTiming);
        cudaEventCreateWithFlags(&evDeg, cudaEventDisableTiming);
        cudaEventCreateWithFlags(&evE1, cudaEventDisableTiming);
        cudaEventCreateWithFlags(&evT, cudaEventDisableTiming);
    }

    const int TB = 256;
    const int nodeBlocks  = (N_NODES + TB - 1) / TB;
    const int node2Blocks = (N_NODES * 2 + TB - 1) / TB;
    const int edgeBlocks  = (E_EDGES + TB - 1) / TB;

    k_fold<<<1, 1024>>>(graph_attr, W_graph, b_graph, W_node, b_node,
                        W_edge_agg, b_edge_agg, W_node_agg, b_node_agg);

    // stream B: degrees, overlapped ONLY with compute-bound k_nodeP
    cudaEventRecord(evFork, 0);
    cudaStreamWaitEvent(sB, evFork, 0);
    k_zeroDeg<<<nodeBlocks, TB, 0, sB>>>();
    k_deg<<<edgeBlocks, TB, 0, sB>>>(edge_index);
    cudaEventRecord(evDeg, sB);

    // main stream
    k_nodeP<<<nodeBlocks, TB>>>(x);
    cudaStreamWaitEvent(0, evDeg, 0);
    k_edge1<<<E1_BLOCKS, TB>>>(edge_index, edge_attr, W_edge_agg);
    cudaEventRecord(evE1, 0);

    // stream B: t accumulation beside node2
    cudaStreamWaitEvent(sB, evE1, 0);
    k_edge2<<<edgeBlocks, TB, 0, sB>>>(edge_index);
    cudaEventRecord(evT, sB);

    k_node2<<<node2Blocks, TB>>>(x, W_node_agg);

    cudaStreamWaitEvent(0, evT, 0);
    k_reduce<<<128, TB>>>();
    k_final<<<1, 32>>>(W_sage_l, b_sage_l, W_sage_r, out);
}